// round 1
// baseline (speedup 1.0000x reference)
#include <cuda_runtime.h>
#include <stdint.h>

// N = 256^3 voxels. d_out layout: [out (N floats)][onehot ch0 (N)][ch1 (N)][ch2 (N)]
#define NVOX (256u * 256u * 256u)

__global__ __launch_bounds__(256, 8)
void yibei_synth_kernel(const int*   __restrict__ labels,
                        const float* __restrict__ id_intensity,
                        const int*   __restrict__ id_is_dark,
                        const float* __restrict__ par,
                        float*       __restrict__ out)
{
    // Combined LUT: .x = scaling (id 0 -> 1.0), .y = class (0=bg, 1=dark, 2=bright)
    __shared__ float2 lut[256];
    const int t = threadIdx.x;   // blockDim.x == 256
    {
        float s = (t == 0) ? 1.0f : __ldg(id_intensity + t);
        float c = (t == 0) ? 0.0f : ((__ldg(id_is_dark + t) == 1) ? 1.0f : 2.0f);
        lut[t] = make_float2(s, c);
    }
    __syncthreads();

    const unsigned i4 = blockIdx.x * 256u + t;          // vec4 index, < NVOX/4
    // NVOX/4 = 4,194,304 ; grid sized exactly — no bounds check needed, but keep it safe
    if (i4 >= NVOX / 4u) return;

    const int4   lab = __ldg(((const int4*)labels) + i4);
    const float4 p   = __ldg(((const float4*)par)  + i4);

    float4 o, h0, h1, h2;

    {
        float2 e = lut[lab.x & 255];
        o.x  = p.x * e.x;
        h0.x = (e.y == 0.0f) ? 1.0f : 0.0f;
        h1.x = (e.y == 1.0f) ? 1.0f : 0.0f;
        h2.x = (e.y == 2.0f) ? 1.0f : 0.0f;
    }
    {
        float2 e = lut[lab.y & 255];
        o.y  = p.y * e.x;
        h0.y = (e.y == 0.0f) ? 1.0f : 0.0f;
        h1.y = (e.y == 1.0f) ? 1.0f : 0.0f;
        h2.y = (e.y == 2.0f) ? 1.0f : 0.0f;
    }
    {
        float2 e = lut[lab.z & 255];
        o.z  = p.z * e.x;
        h0.z = (e.y == 0.0f) ? 1.0f : 0.0f;
        h1.z = (e.y == 1.0f) ? 1.0f : 0.0f;
        h2.z = (e.y == 2.0f) ? 1.0f : 0.0f;
    }
    {
        float2 e = lut[lab.w & 255];
        o.w  = p.w * e.x;
        h0.w = (e.y == 0.0f) ? 1.0f : 0.0f;
        h1.w = (e.y == 1.0f) ? 1.0f : 0.0f;
        h2.w = (e.y == 2.0f) ? 1.0f : 0.0f;
    }

    float4* ovec = (float4*)out;
    const unsigned nv4 = NVOX / 4u;
    ovec[i4]            = o;   // out
    ovec[nv4 + i4]      = h0;  // onehot channel 0 (background)
    ovec[2u * nv4 + i4] = h1;  // onehot channel 1 (dark)
    ovec[3u * nv4 + i4] = h2;  // onehot channel 2 (bright)
}

extern "C" void kernel_launch(void* const* d_in, const int* in_sizes, int n_in,
                              void* d_out, int out_size)
{
    const int*   labels       = (const int*)  d_in[0];
    const float* id_intensity = (const float*)d_in[1];
    const int*   id_is_dark   = (const int*)  d_in[2];
    const float* parenchyma   = (const float*)d_in[3];
    float*       out          = (float*)d_out;

    const unsigned nv4  = NVOX / 4u;          // 4,194,304 vec4 items
    const unsigned grid = nv4 / 256u;          // 16,384 blocks
    yibei_synth_kernel<<<grid, 256>>>(labels, id_intensity, id_is_dark, parenchyma, out);
}